// round 3
// baseline (speedup 1.0000x reference)
#include <cuda_runtime.h>
#include <cuda_fp16.h>

#define CCH 16
#define GSZ 300

// Scratch (allocation-free): planes as fp16 channel-innermost, lines fp32.
__device__ __half g_planes_h[3 * GSZ * GSZ * CCH];   // 8.64 MB, [i][y][x][c]
__device__ float  g_lines_t[3 * GSZ * CCH];          // 57.6 KB, [i][g][c]

struct alignas(8) Half4 { __half2 a, b; };

// ---------------------------------------------------------------------------
// Transpose + quantize planes (3,C,G,G) fp32 -> (3,G,G,C) fp16.
// ---------------------------------------------------------------------------
__global__ void transpose_planes_kernel(const float* __restrict__ planes) {
    int idx = blockIdx.x * blockDim.x + threadIdx.x;     // over 3*G*G texels
    if (idx >= 3 * GSZ * GSZ) return;
    int x  = idx % GSZ;
    int yi = idx / GSZ;
    int y  = yi % GSZ;
    int i  = yi / GSZ;

    const float* src = planes + ((size_t)i * CCH) * GSZ * GSZ + (size_t)y * GSZ + x;
    __half buf[CCH];
#pragma unroll
    for (int c = 0; c < CCH; c++)
        buf[c] = __float2half_rn(__ldg(src + (size_t)c * GSZ * GSZ));

    uint4* dst = reinterpret_cast<uint4*>(g_planes_h + (size_t)idx * CCH);
    const uint4* sp = reinterpret_cast<const uint4*>(buf);
    dst[0] = sp[0];
    dst[1] = sp[1];
}

// Transpose lines (3,C,G) -> (3,G,C), fp32
__global__ void transpose_lines_kernel(const float* __restrict__ lines) {
    int idx = blockIdx.x * blockDim.x + threadIdx.x;     // over 3*G
    if (idx >= 3 * GSZ) return;
    int g = idx % GSZ;
    int i = idx / GSZ;

    float buf[CCH];
#pragma unroll
    for (int c = 0; c < CCH; c++)
        buf[c] = __ldg(lines + ((size_t)i * CCH + c) * GSZ + g);

    float4* dst = reinterpret_cast<float4*>(g_lines_t + (size_t)idx * CCH);
#pragma unroll
    for (int c4 = 0; c4 < CCH / 4; c4++)
        dst[c4] = make_float4(buf[4 * c4 + 0], buf[4 * c4 + 1],
                              buf[4 * c4 + 2], buf[4 * c4 + 3]);
}

// ---------------------------------------------------------------------------
// Sampler: 8 lanes per point. lane = p*8 + xb*4 + r
//   p  : point within warp (0..3)
//   xb : selects x0/x1 (and z0/z1 for lines)
//   r  : channel quad (0..3)
// Bilinear x-pair combined via shfl_xor(4). Outputs staged in smem, then
// written fully coalesced (128B per channel row per block of 32 points).
// ---------------------------------------------------------------------------
__device__ __forceinline__ void lerp_idx(float coord, int& i0, int& i1, float& w) {
    float x  = (coord + 1.0f) * 0.5f * (float)(GSZ - 1);
    float xf = floorf(x);
    xf = fminf(fmaxf(xf, 0.0f), (float)(GSZ - 1));
    i0 = (int)xf;
    i1 = min(i0 + 1, GSZ - 1);
    w  = x - xf;
}

__global__ __launch_bounds__(256) void vm_sample_kernel(
        const float* __restrict__ xyz, float* __restrict__ out, int N) {
    __shared__ float s[32][50];   // [point_in_block][channel], padded

    int tid    = threadIdx.x;
    int warpId = tid >> 5;
    int lane   = tid & 31;
    int p  = lane >> 3;
    int xb = (lane >> 2) & 1;
    int r  = lane & 3;

    int blockBase = blockIdx.x * 32;
    int wBase     = blockBase + warpId * 4;

    // Coalesced coord fetch: lanes 0..11 read 4 points * 3 coords
    float v = 0.0f;
    {
        long long gi = (long long)wBase * 3 + lane;
        if (lane < 12 && gi < (long long)N * 3)
            v = __ldg(xyz + gi);
    }
    float c0 = __shfl_sync(0xffffffffu, v, p * 3 + 0);
    float c1 = __shfl_sync(0xffffffffu, v, p * 3 + 1);
    float c2 = __shfl_sync(0xffffffffu, v, p * 3 + 2);
    float coords[3] = {c0, c1, c2};   // zero for out-of-range points -> safe idx

    int i0[3], i1[3];
    float w[3];
#pragma unroll
    for (int d = 0; d < 3; d++)
        lerp_idx(coords[d], i0[d], i1[d], w[d]);

    // matMode = ((1,2),(0,2),(0,1))
    const int ma[3] = {1, 0, 0};
    const int mb[3] = {2, 2, 1};

#pragma unroll
    for (int i = 0; i < 3; i++) {
        int a = ma[i], b = mb[i];
        int x0 = i0[a], x1 = i1[a];
        int y0 = i0[b], y1 = i1[b];
        int z0 = i0[i], z1 = i1[i];
        float wx = w[a], wy = w[b], wz = w[i];

        int xl = xb ? x1 : x0;
        int zl = xb ? z1 : z0;

        // plane rows y0, y1: 8B half4 loads, (x0,x1) contiguous per point
        const Half4* pa = reinterpret_cast<const Half4*>(
            g_planes_h + (((size_t)i * GSZ + y0) * GSZ + xl) * CCH + r * 4);
        const Half4* pb = reinterpret_cast<const Half4*>(
            g_planes_h + (((size_t)i * GSZ + y1) * GSZ + xl) * CCH + r * 4);
        Half4 ha = *pa;
        Half4 hb = *pb;
        float2 a01 = __half22float2(ha.a);
        float2 a23 = __half22float2(ha.b);
        float2 b01 = __half22float2(hb.a);
        float2 b23 = __half22float2(hb.b);

        float wsel = xb ? wx : (1.0f - wx);
        float wy0  = 1.0f - wy;

        float q0 = (a01.x * wy0 + b01.x * wy) * wsel;
        float q1 = (a01.y * wy0 + b01.y * wy) * wsel;
        float q2 = (a23.x * wy0 + b23.x * wy) * wsel;
        float q3 = (a23.y * wy0 + b23.y * wy) * wsel;

        // combine x0/x1 partials across xb lanes
        q0 += __shfl_xor_sync(0xffffffffu, q0, 4);
        q1 += __shfl_xor_sync(0xffffffffu, q1, 4);
        q2 += __shfl_xor_sync(0xffffffffu, q2, 4);
        q3 += __shfl_xor_sync(0xffffffffu, q3, 4);

        // line: lane xb loads z0/z1 quad r, combine across xb lanes
        const float4* lp = reinterpret_cast<const float4*>(
            g_lines_t + ((size_t)i * GSZ + zl) * CCH + r * 4);
        float4 lf = *lp;
        float lsel = xb ? wz : (1.0f - wz);
        float l0 = lf.x * lsel, l1 = lf.y * lsel, l2 = lf.z * lsel, l3 = lf.w * lsel;
        l0 += __shfl_xor_sync(0xffffffffu, l0, 4);
        l1 += __shfl_xor_sync(0xffffffffu, l1, 4);
        l2 += __shfl_xor_sync(0xffffffffu, l2, 4);
        l3 += __shfl_xor_sync(0xffffffffu, l3, 4);

        float res[4] = {q0 * l0, q1 * l1, q2 * l2, q3 * l3};

        // lane (xb) stores components 2*xb, 2*xb+1 of its quad
        int pt = warpId * 4 + p;
        int cc = i * CCH + r * 4 + xb * 2;
        s[pt][cc + 0] = res[2 * xb + 0];
        s[pt][cc + 1] = res[2 * xb + 1];
    }

    __syncthreads();

    // Coalesced write-out: 48 channels x 32 points
#pragma unroll
    for (int k = 0; k < 6; k++) {
        int idx = k * 256 + tid;
        int c  = idx >> 5;          // 0..47
        int pt = idx & 31;
        int nn = blockBase + pt;
        if (nn < N)
            out[(size_t)c * N + nn] = s[pt][c];
    }
}

extern "C" void kernel_launch(void* const* d_in, const int* in_sizes, int n_in,
                              void* d_out, int out_size) {
    const float* xyz    = (const float*)d_in[0];
    const float* planes = (const float*)d_in[1];
    const float* lines  = (const float*)d_in[2];
    float* out = (float*)d_out;

    int N = in_sizes[0] / 3;

    {
        int total = 3 * GSZ * GSZ;
        int threads = 256;
        transpose_planes_kernel<<<(total + threads - 1) / threads, threads>>>(planes);
    }
    {
        int total = 3 * GSZ;
        int threads = 256;
        transpose_lines_kernel<<<(total + threads - 1) / threads, threads>>>(lines);
    }
    {
        int blocks = (N + 31) / 32;   // 32 points per 256-thread block
        vm_sample_kernel<<<blocks, 256>>>(xyz, out, N);
    }
}